// round 7
// baseline (speedup 1.0000x reference)
#include <cuda_runtime.h>

#define DIM      64
#define KC       512
#define ROWS     64           // z rows per tile
#define KCHUNK   64           // codebook codes per smem chunk
#define NCHUNK   (KC / KCHUNK)
#define NTHREADS 256
#define ZS_LD    68           // pad: stride 68 floats = 272B (16B-aligned, conflict-free)
#define ES_LD    68

__global__ void __launch_bounds__(NTHREADS)
vq_kernel(const float* __restrict__ z, const float* __restrict__ cb,
          float* __restrict__ out, int n_rows) {
    __shared__ __align__(16) float ZS[DIM * ZS_LD];   // z tile transposed [d][row]
    __shared__ __align__(16) float ES[DIM * ES_LD];   // cb chunk transposed [d][k]
    __shared__ __align__(16) float CN[KC];            // ||e_k||^2
    __shared__ __align__(16) float ZN[ROWS];          // ||z_r||^2

    const int tid = threadIdx.x;
    const int tx  = tid & 15;     // code lane: 4 codes
    const int ty  = tid >> 4;     // row group: 4 rows

    // Codebook norms, reference rounding order (rounded mul, rounded add, d ascending).
    for (int k = tid; k < KC; k += NTHREADS) {
        const float* row = cb + k * DIM;
        float acc = 0.f;
        #pragma unroll 1
        for (int d = 0; d < DIM; d++) {
            float e = row[d];
            acc = __fadd_rn(acc, __fmul_rn(e, e));
        }
        CN[k] = acc;
    }

    const int ntiles = n_rows / ROWS;
    for (int tile = blockIdx.x; tile < ntiles; tile += gridDim.x) {
        __syncthreads();   // prior tile's readers done; CN visible on first pass
        const float* zt = z + (size_t)tile * (ROWS * DIM);
        // Load z tile transposed into ZS.
        for (int i = tid; i < ROWS * DIM / 4; i += NTHREADS) {
            float4 v = reinterpret_cast<const float4*>(zt)[i];
            int r  = i >> 4;            // (4i)/64
            int d0 = (i & 15) * 4;
            ZS[(d0 + 0) * ZS_LD + r] = v.x;
            ZS[(d0 + 1) * ZS_LD + r] = v.y;
            ZS[(d0 + 2) * ZS_LD + r] = v.z;
            ZS[(d0 + 3) * ZS_LD + r] = v.w;
        }
        __syncthreads();
        // Row norms, same sequential rounding chain as reference's sum(z*z).
        if (tid < ROWS) {
            float acc = 0.f;
            #pragma unroll 1
            for (int d = 0; d < DIM; d++) {
                float a = ZS[d * ZS_LD + tid];
                acc = __fadd_rn(acc, __fmul_rn(a, a));
            }
            ZN[tid] = acc;
        }
        // (ZN published by the sync at the top of the chunk loop)

        float minv[4]; int mini[4];
        #pragma unroll
        for (int i = 0; i < 4; i++) { minv[i] = __int_as_float(0x7f800000); mini[i] = 0; }

        #pragma unroll 1
        for (int kc = 0; kc < NCHUNK; kc++) {
            __syncthreads();   // previous chunk's ES readers done (also publishes ZN on kc=0)
            // Load codebook chunk transposed into ES (L1-hot after first tile).
            const float* cbc = cb + (size_t)(kc * KCHUNK) * DIM;
            for (int i = tid; i < KCHUNK * DIM / 4; i += NTHREADS) {
                float4 v = reinterpret_cast<const float4*>(cbc)[i];
                int kl = i >> 4;
                int d0 = (i & 15) * 4;
                ES[(d0 + 0) * ES_LD + kl] = v.x;
                ES[(d0 + 1) * ES_LD + kl] = v.y;
                ES[(d0 + 2) * ES_LD + kl] = v.z;
                ES[(d0 + 3) * ES_LD + kl] = v.w;
            }
            __syncthreads();

            // 4x4 microtile GEMM: dot[row i][code j], sequential d, fused FFMA.
            float acc[4][4];
            #pragma unroll
            for (int i = 0; i < 4; i++)
                #pragma unroll
                for (int j = 0; j < 4; j++) acc[i][j] = 0.f;

            const float* zp = ZS + ty * 4;
            const float* ep = ES + tx * 4;
            #pragma unroll 4
            for (int d = 0; d < DIM; d++) {
                float4 a = *reinterpret_cast<const float4*>(zp + d * ZS_LD);
                float4 b = *reinterpret_cast<const float4*>(ep + d * ES_LD);
                float av[4] = {a.x, a.y, a.z, a.w};
                float bv[4] = {b.x, b.y, b.z, b.w};
                #pragma unroll
                for (int i = 0; i < 4; i++)
                    #pragma unroll
                    for (int j = 0; j < 4; j++)
                        acc[i][j] = __fmaf_rn(av[i], bv[j], acc[i][j]);
            }

            // Epilogue: s = fl(fl(zn - 2*dot) + cn); running argmin, ascending k,
            // strict < keeps the first (lowest) index like jnp.argmin.
            const int kbase = kc * KCHUNK + tx * 4;
            #pragma unroll
            for (int i = 0; i < 4; i++) {
                float zn = ZN[ty * 4 + i];
                #pragma unroll
                for (int j = 0; j < 4; j++) {
                    float cn = CN[kbase + j];
                    float t  = __fadd_rn(zn, __fmul_rn(-2.0f, acc[i][j]));
                    float s  = __fadd_rn(t, cn);
                    if (s < minv[i]) { minv[i] = s; mini[i] = kbase + j; }
                }
            }
        }

        // Reduce across the 16 code-lanes sharing each row group (lower index wins ties).
        #pragma unroll
        for (int i = 0; i < 4; i++) {
            float v  = minv[i];
            int  idx = mini[i];
            #pragma unroll
            for (int off = 8; off > 0; off >>= 1) {
                float vo = __shfl_xor_sync(0xffffffffu, v, off);
                int   io = __shfl_xor_sync(0xffffffffu, idx, off);
                if (vo < v || (vo == v && io < idx)) { v = vo; idx = io; }
            }
            // Output buffer is float32 (indices compared as floats) — exact for idx<=511.
            if (tx == 0) out[tile * ROWS + ty * 4 + i] = (float)idx;
        }
    }
}

extern "C" void kernel_launch(void* const* d_in, const int* in_sizes, int n_in,
                              void* d_out, int out_size) {
    // Identify inputs by size: codebook has exactly KC*DIM = 32768 elements.
    int cb_idx = (n_in > 1 && in_sizes[1] == KC * DIM) ? 1 : 0;
    int z_idx  = 1 - cb_idx;
    const float* z  = (const float*)d_in[z_idx];    // z_e_x  [32,4096,64] f32
    const float* cb = (const float*)d_in[cb_idx];   // codebook [512,64]  f32
    int n_rows = in_sizes[z_idx] / DIM;             // 131072

    vq_kernel<<<296, NTHREADS>>>(z, cb, (float*)d_out, n_rows);
}